// round 2
// baseline (speedup 1.0000x reference)
#include <cuda_runtime.h>

// ActionNetwork: B=262144 rows, N=8, M=1. 80 f32 in -> 128 f32 out per row.
// R2: occupancy fix. Input buffer reused for output staging (queue kept in
// registers), g[] recomputed instead of stored, __launch_bounds__(256,2)
// -> 2 blocks/SM (regs<=128, smem 88.5KB).

constexpr int TPB = 256;
constexpr int ROW = 80;          // floats per input row
constexpr int OROW = 128;        // floats per output row
constexpr int INSTRIDE = 84;     // input smem row stride (floats)
constexpr int OUTSTRIDE = 132;   // output smem row stride (floats)

// params layout at sm[0..632)
constexpr int P_W0 = 0;        // 8 rows x 20 (padded from 18) = 160
constexpr int P_B0 = 160;
constexpr int P_W1 = 168;
constexpr int P_B1 = 232;
constexpr int P_DIST = 240;
constexpr int P_QP = 304;
constexpr int P_DEP = 368;
constexpr int P_ARR = 432;
constexpr int P_MINIF = 496;
constexpr int P_INTF = 504;
constexpr int P_PRICE = 568;
constexpr int P_TOTAL = 632;

constexpr int BUF = P_TOTAL;                       // shared in/out staging buffer
constexpr int BUF_FLOATS = TPB * INSTRIDE;         // 21504 >= 128*132=16896
constexpr int SMEM_FLOATS = BUF + BUF_FLOATS;      // 22136
constexpr int SMEM_BYTES = SMEM_FLOATS * 4;        // 88544

__global__ __launch_bounds__(TPB, 2)
void actnet_kernel(const float* __restrict__ x,
                   const float* __restrict__ W0, const float* __restrict__ b0,
                   const float* __restrict__ W1, const float* __restrict__ b1,
                   const float* __restrict__ distp, const float* __restrict__ qp,
                   const float* __restrict__ depf, const float* __restrict__ arrf,
                   const float* __restrict__ minif, const float* __restrict__ intf,
                   const float* __restrict__ pricef,
                   float* __restrict__ out)
{
    extern __shared__ float sm[];
    const int tid = threadIdx.x;
    const int blk = blockIdx.x;

    // ---- stage params (broadcast reads, once per block) ----
    float* Wp = sm;
    for (int idx = tid; idx < 144; idx += TPB)
        Wp[P_W0 + (idx / 18) * 20 + (idx % 18)] = W0[idx];
    for (int idx = tid; idx < 16; idx += TPB)
        Wp[P_W0 + (idx >> 1) * 20 + 18 + (idx & 1)] = 0.0f;
    for (int idx = tid; idx < 8; idx += TPB) {
        Wp[P_B0 + idx] = b0[idx];
        Wp[P_B1 + idx] = b1[idx];
        Wp[P_MINIF + idx] = minif[idx];
    }
    for (int idx = tid; idx < 64; idx += TPB) {
        Wp[P_W1 + idx] = W1[idx];
        Wp[P_DIST + idx] = distp[idx];
        Wp[P_QP + idx] = qp[idx];
        Wp[P_DEP + idx] = depf[idx];
        Wp[P_ARR + idx] = arrf[idx];
        Wp[P_INTF + idx] = intf[idx];
        Wp[P_PRICE + idx] = pricef[idx];
    }

    // ---- stage input: coalesced float4 loads -> padded smem rows ----
    const float4* x4 = (const float4*)x + (size_t)blk * (TPB * ROW / 4);
    #pragma unroll
    for (int k = 0; k < ROW / 4; k++) {            // 20 iterations
        int g = tid + k * TPB;
        float4 v = __ldg(&x4[g]);
        int row = g / 20;
        int col = (g % 20) * 4;
        *(float4*)&sm[BUF + row * INSTRIDE + col] = v;
    }
    __syncthreads();

    // ---- pull my entire row into registers (input smem dead afterwards) ----
    const float* myrow = &sm[BUF + tid * INSTRIDE];
    float veh[8], mini[8], q[64];
    #pragma unroll
    for (int k = 0; k < 2; k++) {
        float4 v = *(const float4*)&myrow[k * 4];
        float4 m = *(const float4*)&myrow[8 + k * 4];
        veh[k * 4 + 0] = v.x; veh[k * 4 + 1] = v.y; veh[k * 4 + 2] = v.z; veh[k * 4 + 3] = v.w;
        mini[k * 4 + 0] = m.x; mini[k * 4 + 1] = m.y; mini[k * 4 + 2] = m.z; mini[k * 4 + 3] = m.w;
    }
    #pragma unroll
    for (int k = 0; k < 16; k++) {
        float4 v = *(const float4*)&myrow[16 + k * 4];
        q[k * 4 + 0] = v.x; q[k * 4 + 1] = v.y; q[k * 4 + 2] = v.z; q[k * 4 + 3] = v.w;
    }

    // ---- p[i] = b0 + veh*W0[:,0] + mini*W0[:,1] + q[i,:]·W0[i,2:10] + q[:,i]·W0[:,10+r] ----
    float p[8];
    #pragma unroll
    for (int i = 0; i < 8; i++)
        p[i] = Wp[P_B0 + i] + veh[i] * Wp[P_W0 + i * 20 + 0] + mini[i] * Wp[P_W0 + i * 20 + 1];
    #pragma unroll
    for (int r = 0; r < 8; r++) {
        const float* w0r = &Wp[P_W0 + r * 20];
        #pragma unroll
        for (int c = 0; c < 8; c++) p[r] += q[r * 8 + c] * w0r[2 + c];
        #pragma unroll
        for (int i = 0; i < 8; i++) p[i] += q[r * 8 + i] * Wp[P_W0 + i * 20 + 10 + r];
    }

    // ---- potential = p @ W1^T + b1 ----
    float pot[8];
    #pragma unroll
    for (int i = 0; i < 8; i++) {
        float a = Wp[P_B1 + i];
        #pragma unroll
        for (int k = 0; k < 8; k++) a += p[k] * Wp[P_W1 + i * 8 + k];
        pot[i] = a;
    }

    // ---- remain, inv, scale (g recomputed, not stored) ----
    float remain[8], inv[8], scale[8];
    #pragma unroll
    for (int i = 0; i < 8; i++) {
        float rs = 0.0f;
        #pragma unroll
        for (int j = 0; j < 8; j++) {
            float gv = fmaxf(pot[i] - pot[j], 0.0f) * Wp[P_DIST + i * 8 + j]
                     + q[i * 8 + j] * Wp[P_QP + i * 8 + j];
            rs += gv;
        }
        float rem = fmaxf(veh[i] - rs, 0.0f);
        remain[i] = rem;
        float tot = fmaxf(rs + rem - 0.001f, 0.0f) + 0.001f;
        inv[i] = 1.0f / tot;
        scale[i] = veh[i] * inv[i];
    }

    // ---- departure, arrival, intentions (recompute gv) ----
    float arrival[8];
    #pragma unroll
    for (int j = 0; j < 8; j++) arrival[j] = mini[j] * Wp[P_MINIF + j];
    float no_remain[8];
    {
        float departure[8], intents[8];
        #pragma unroll
        for (int i = 0; i < 8; i++) {
            float sc = scale[i];
            float dsum = 0.0f, isum = 0.0f;
            #pragma unroll
            for (int j = 0; j < 8; j++) {
                float gv = fmaxf(pot[i] - pot[j], 0.0f) * Wp[P_DIST + i * 8 + j]
                         + q[i * 8 + j] * Wp[P_QP + i * 8 + j];
                if (j == i) gv += remain[i];
                float raw = gv * sc;
                dsum += raw * Wp[P_DEP + i * 8 + j];
                arrival[j] += raw * Wp[P_ARR + i * 8 + j];
                float fg = fmaxf(gv - raw, 0.0f);
                isum += fg * Wp[P_INTF + i * 8 + j];
            }
            departure[i] = dsum;
            intents[i] = isum;
        }
        #pragma unroll
        for (int i = 0; i < 8; i++) {
            float fv = veh[i] - departure[i] + arrival[i];
            no_remain[i] = fmaxf(fv - intents[i], 0.0f) * (1.0f / 7.0f);
        }
    }

    // ---- output: two 128-row chunks staged into the (now dead) input buffer ----
    __syncthreads();   // all threads finished reading input smem
    #pragma unroll 1
    for (int chunk = 0; chunk < 2; chunk++) {
        if ((tid >> 7) == chunk) {
            float* orow = &sm[BUF + (tid & 127) * OUTSTRIDE];
            #pragma unroll
            for (int i = 0; i < 8; i++) {
                float sc = scale[i], iv = inv[i], nr = no_remain[i];
                float av[8], pv[8];
                #pragma unroll
                for (int j = 0; j < 8; j++) {
                    float gv = fmaxf(pot[i] - pot[j], 0.0f) * Wp[P_DIST + i * 8 + j]
                             + q[i * 8 + j] * Wp[P_QP + i * 8 + j];
                    if (j == i) gv += remain[i];
                    av[j] = gv * iv;
                    float raw = gv * sc;
                    float fg = fmaxf(gv - raw, 0.0f);
                    float fq = fmaxf(q[i * 8 + j] - raw, 0.0f);
                    float it = fg + nr - fq;
                    pv[j] = fmaxf(1.0f - fmaxf(it * Wp[P_PRICE + i * 8 + j], 0.0f) - 0.6f, 0.0f) + 0.6f;
                }
                *(float4*)&orow[i * 16 + 0]  = make_float4(av[0], av[1], av[2], av[3]);
                *(float4*)&orow[i * 16 + 4]  = make_float4(av[4], av[5], av[6], av[7]);
                *(float4*)&orow[i * 16 + 8]  = make_float4(pv[0], pv[1], pv[2], pv[3]);
                *(float4*)&orow[i * 16 + 12] = make_float4(pv[4], pv[5], pv[6], pv[7]);
            }
        }
        __syncthreads();
        // flush 128 rows * 128 floats = 4096 float4, fully coalesced
        float4* out4 = (float4*)out + ((size_t)blk * TPB + chunk * 128) * (OROW / 4);
        #pragma unroll
        for (int k = 0; k < 16; k++) {
            int g4 = tid + k * TPB;
            int lrow = g4 >> 5;
            int col4 = g4 & 31;
            out4[g4] = *(const float4*)&sm[BUF + lrow * OUTSTRIDE + col4 * 4];
        }
        __syncthreads();
    }
}

extern "C" void kernel_launch(void* const* d_in, const int* in_sizes, int n_in,
                              void* d_out, int out_size) {
    const float* x      = (const float*)d_in[0];
    const float* W0     = (const float*)d_in[1];
    const float* b0     = (const float*)d_in[2];
    const float* W1     = (const float*)d_in[3];
    const float* b1     = (const float*)d_in[4];
    const float* distp  = (const float*)d_in[5];
    const float* qp     = (const float*)d_in[6];
    const float* depf   = (const float*)d_in[7];
    const float* arrf   = (const float*)d_in[8];
    const float* minif  = (const float*)d_in[9];
    const float* intf   = (const float*)d_in[10];
    const float* pricef = (const float*)d_in[11];
    float* out = (float*)d_out;

    int B = in_sizes[0] / ROW;          // 262144
    int grid = B / TPB;                 // 1024

    cudaFuncSetAttribute(actnet_kernel, cudaFuncAttributeMaxDynamicSharedMemorySize, SMEM_BYTES);
    actnet_kernel<<<grid, TPB, SMEM_BYTES>>>(x, W0, b0, W1, b1, distp, qp, depf, arrf,
                                             minif, intf, pricef, out);
}

// round 3
// speedup vs baseline: 1.0007x; 1.0007x over previous
#include <cuda_runtime.h>

// ActionNetwork: B=262144 rows, N=8, M=1. 80 f32 in -> 128 f32 out per row.
// R2: occupancy fix. Input buffer reused for output staging (queue kept in
// registers), g[] recomputed instead of stored, __launch_bounds__(256,2)
// -> 2 blocks/SM (regs<=128, smem 88.5KB).

constexpr int TPB = 256;
constexpr int ROW = 80;          // floats per input row
constexpr int OROW = 128;        // floats per output row
constexpr int INSTRIDE = 84;     // input smem row stride (floats)
constexpr int OUTSTRIDE = 132;   // output smem row stride (floats)

// params layout at sm[0..632)
constexpr int P_W0 = 0;        // 8 rows x 20 (padded from 18) = 160
constexpr int P_B0 = 160;
constexpr int P_W1 = 168;
constexpr int P_B1 = 232;
constexpr int P_DIST = 240;
constexpr int P_QP = 304;
constexpr int P_DEP = 368;
constexpr int P_ARR = 432;
constexpr int P_MINIF = 496;
constexpr int P_INTF = 504;
constexpr int P_PRICE = 568;
constexpr int P_TOTAL = 632;

constexpr int BUF = P_TOTAL;                       // shared in/out staging buffer
constexpr int BUF_FLOATS = TPB * INSTRIDE;         // 21504 >= 128*132=16896
constexpr int SMEM_FLOATS = BUF + BUF_FLOATS;      // 22136
constexpr int SMEM_BYTES = SMEM_FLOATS * 4;        // 88544

__global__ __launch_bounds__(TPB, 2)
void actnet_kernel(const float* __restrict__ x,
                   const float* __restrict__ W0, const float* __restrict__ b0,
                   const float* __restrict__ W1, const float* __restrict__ b1,
                   const float* __restrict__ distp, const float* __restrict__ qp,
                   const float* __restrict__ depf, const float* __restrict__ arrf,
                   const float* __restrict__ minif, const float* __restrict__ intf,
                   const float* __restrict__ pricef,
                   float* __restrict__ out)
{
    extern __shared__ float sm[];
    const int tid = threadIdx.x;
    const int blk = blockIdx.x;

    // ---- stage params (broadcast reads, once per block) ----
    float* Wp = sm;
    for (int idx = tid; idx < 144; idx += TPB)
        Wp[P_W0 + (idx / 18) * 20 + (idx % 18)] = W0[idx];
    for (int idx = tid; idx < 16; idx += TPB)
        Wp[P_W0 + (idx >> 1) * 20 + 18 + (idx & 1)] = 0.0f;
    for (int idx = tid; idx < 8; idx += TPB) {
        Wp[P_B0 + idx] = b0[idx];
        Wp[P_B1 + idx] = b1[idx];
        Wp[P_MINIF + idx] = minif[idx];
    }
    for (int idx = tid; idx < 64; idx += TPB) {
        Wp[P_W1 + idx] = W1[idx];
        Wp[P_DIST + idx] = distp[idx];
        Wp[P_QP + idx] = qp[idx];
        Wp[P_DEP + idx] = depf[idx];
        Wp[P_ARR + idx] = arrf[idx];
        Wp[P_INTF + idx] = intf[idx];
        Wp[P_PRICE + idx] = pricef[idx];
    }

    // ---- stage input: coalesced float4 loads -> padded smem rows ----
    const float4* x4 = (const float4*)x + (size_t)blk * (TPB * ROW / 4);
    #pragma unroll
    for (int k = 0; k < ROW / 4; k++) {            // 20 iterations
        int g = tid + k * TPB;
        float4 v = __ldg(&x4[g]);
        int row = g / 20;
        int col = (g % 20) * 4;
        *(float4*)&sm[BUF + row * INSTRIDE + col] = v;
    }
    __syncthreads();

    // ---- pull my entire row into registers (input smem dead afterwards) ----
    const float* myrow = &sm[BUF + tid * INSTRIDE];
    float veh[8], mini[8], q[64];
    #pragma unroll
    for (int k = 0; k < 2; k++) {
        float4 v = *(const float4*)&myrow[k * 4];
        float4 m = *(const float4*)&myrow[8 + k * 4];
        veh[k * 4 + 0] = v.x; veh[k * 4 + 1] = v.y; veh[k * 4 + 2] = v.z; veh[k * 4 + 3] = v.w;
        mini[k * 4 + 0] = m.x; mini[k * 4 + 1] = m.y; mini[k * 4 + 2] = m.z; mini[k * 4 + 3] = m.w;
    }
    #pragma unroll
    for (int k = 0; k < 16; k++) {
        float4 v = *(const float4*)&myrow[16 + k * 4];
        q[k * 4 + 0] = v.x; q[k * 4 + 1] = v.y; q[k * 4 + 2] = v.z; q[k * 4 + 3] = v.w;
    }

    // ---- p[i] = b0 + veh*W0[:,0] + mini*W0[:,1] + q[i,:]·W0[i,2:10] + q[:,i]·W0[:,10+r] ----
    float p[8];
    #pragma unroll
    for (int i = 0; i < 8; i++)
        p[i] = Wp[P_B0 + i] + veh[i] * Wp[P_W0 + i * 20 + 0] + mini[i] * Wp[P_W0 + i * 20 + 1];
    #pragma unroll
    for (int r = 0; r < 8; r++) {
        const float* w0r = &Wp[P_W0 + r * 20];
        #pragma unroll
        for (int c = 0; c < 8; c++) p[r] += q[r * 8 + c] * w0r[2 + c];
        #pragma unroll
        for (int i = 0; i < 8; i++) p[i] += q[r * 8 + i] * Wp[P_W0 + i * 20 + 10 + r];
    }

    // ---- potential = p @ W1^T + b1 ----
    float pot[8];
    #pragma unroll
    for (int i = 0; i < 8; i++) {
        float a = Wp[P_B1 + i];
        #pragma unroll
        for (int k = 0; k < 8; k++) a += p[k] * Wp[P_W1 + i * 8 + k];
        pot[i] = a;
    }

    // ---- remain, inv, scale (g recomputed, not stored) ----
    float remain[8], inv[8], scale[8];
    #pragma unroll
    for (int i = 0; i < 8; i++) {
        float rs = 0.0f;
        #pragma unroll
        for (int j = 0; j < 8; j++) {
            float gv = fmaxf(pot[i] - pot[j], 0.0f) * Wp[P_DIST + i * 8 + j]
                     + q[i * 8 + j] * Wp[P_QP + i * 8 + j];
            rs += gv;
        }
        float rem = fmaxf(veh[i] - rs, 0.0f);
        remain[i] = rem;
        float tot = fmaxf(rs + rem - 0.001f, 0.0f) + 0.001f;
        inv[i] = 1.0f / tot;
        scale[i] = veh[i] * inv[i];
    }

    // ---- departure, arrival, intentions (recompute gv) ----
    float arrival[8];
    #pragma unroll
    for (int j = 0; j < 8; j++) arrival[j] = mini[j] * Wp[P_MINIF + j];
    float no_remain[8];
    {
        float departure[8], intents[8];
        #pragma unroll
        for (int i = 0; i < 8; i++) {
            float sc = scale[i];
            float dsum = 0.0f, isum = 0.0f;
            #pragma unroll
            for (int j = 0; j < 8; j++) {
                float gv = fmaxf(pot[i] - pot[j], 0.0f) * Wp[P_DIST + i * 8 + j]
                         + q[i * 8 + j] * Wp[P_QP + i * 8 + j];
                if (j == i) gv += remain[i];
                float raw = gv * sc;
                dsum += raw * Wp[P_DEP + i * 8 + j];
                arrival[j] += raw * Wp[P_ARR + i * 8 + j];
                float fg = fmaxf(gv - raw, 0.0f);
                isum += fg * Wp[P_INTF + i * 8 + j];
            }
            departure[i] = dsum;
            intents[i] = isum;
        }
        #pragma unroll
        for (int i = 0; i < 8; i++) {
            float fv = veh[i] - departure[i] + arrival[i];
            no_remain[i] = fmaxf(fv - intents[i], 0.0f) * (1.0f / 7.0f);
        }
    }

    // ---- output: two 128-row chunks staged into the (now dead) input buffer ----
    __syncthreads();   // all threads finished reading input smem
    #pragma unroll 1
    for (int chunk = 0; chunk < 2; chunk++) {
        if ((tid >> 7) == chunk) {
            float* orow = &sm[BUF + (tid & 127) * OUTSTRIDE];
            #pragma unroll
            for (int i = 0; i < 8; i++) {
                float sc = scale[i], iv = inv[i], nr = no_remain[i];
                float av[8], pv[8];
                #pragma unroll
                for (int j = 0; j < 8; j++) {
                    float gv = fmaxf(pot[i] - pot[j], 0.0f) * Wp[P_DIST + i * 8 + j]
                             + q[i * 8 + j] * Wp[P_QP + i * 8 + j];
                    if (j == i) gv += remain[i];
                    av[j] = gv * iv;
                    float raw = gv * sc;
                    float fg = fmaxf(gv - raw, 0.0f);
                    float fq = fmaxf(q[i * 8 + j] - raw, 0.0f);
                    float it = fg + nr - fq;
                    pv[j] = fmaxf(1.0f - fmaxf(it * Wp[P_PRICE + i * 8 + j], 0.0f) - 0.6f, 0.0f) + 0.6f;
                }
                *(float4*)&orow[i * 16 + 0]  = make_float4(av[0], av[1], av[2], av[3]);
                *(float4*)&orow[i * 16 + 4]  = make_float4(av[4], av[5], av[6], av[7]);
                *(float4*)&orow[i * 16 + 8]  = make_float4(pv[0], pv[1], pv[2], pv[3]);
                *(float4*)&orow[i * 16 + 12] = make_float4(pv[4], pv[5], pv[6], pv[7]);
            }
        }
        __syncthreads();
        // flush 128 rows * 128 floats = 4096 float4, fully coalesced
        float4* out4 = (float4*)out + ((size_t)blk * TPB + chunk * 128) * (OROW / 4);
        #pragma unroll
        for (int k = 0; k < 16; k++) {
            int g4 = tid + k * TPB;
            int lrow = g4 >> 5;
            int col4 = g4 & 31;
            out4[g4] = *(const float4*)&sm[BUF + lrow * OUTSTRIDE + col4 * 4];
        }
        __syncthreads();
    }
}

extern "C" void kernel_launch(void* const* d_in, const int* in_sizes, int n_in,
                              void* d_out, int out_size) {
    const float* x      = (const float*)d_in[0];
    const float* W0     = (const float*)d_in[1];
    const float* b0     = (const float*)d_in[2];
    const float* W1     = (const float*)d_in[3];
    const float* b1     = (const float*)d_in[4];
    const float* distp  = (const float*)d_in[5];
    const float* qp     = (const float*)d_in[6];
    const float* depf   = (const float*)d_in[7];
    const float* arrf   = (const float*)d_in[8];
    const float* minif  = (const float*)d_in[9];
    const float* intf   = (const float*)d_in[10];
    const float* pricef = (const float*)d_in[11];
    float* out = (float*)d_out;

    int B = in_sizes[0] / ROW;          // 262144
    int grid = B / TPB;                 // 1024

    cudaFuncSetAttribute(actnet_kernel, cudaFuncAttributeMaxDynamicSharedMemorySize, SMEM_BYTES);
    actnet_kernel<<<grid, TPB, SMEM_BYTES>>>(x, W0, b0, W1, b1, distp, qp, depf, arrf,
                                             minif, intf, pricef, out);
}

// round 5
// speedup vs baseline: 1.1467x; 1.1460x over previous
#include <cuda_runtime.h>

// ActionNetwork: B=262144 rows, N=8, M=1. 80 f32 in -> 128 f32 out per row.
// R4 (= R3 re-bench after infra failure): TPB=128 x 3 blocks/SM (<=168 regs,
// no spills), vectorized (float4) param loads from restructured smem layout,
// q in registers, input buffer reused for full-width output staging.

constexpr int TPB = 128;
constexpr int ROW = 80;          // floats per input row
constexpr int OROW = 128;        // floats per output row
constexpr int INSTRIDE = 84;     // input smem row stride (floats)
constexpr int OUTSTRIDE = 132;   // output smem row stride (floats)

// params layout at sm[0..616), every 8-float row 16B-aligned
constexpr int P_W0A  = 0;     // W0[:,0]          (8)
constexpr int P_W0B  = 8;     // W0[:,1]          (8)
constexpr int P_W0R  = 16;    // W0[:,2:10]  8x8  (64)
constexpr int P_W0T  = 80;    // W0[:,10:18] 8x8  (64)
constexpr int P_B0   = 144;   // (8)
constexpr int P_W1   = 152;   // (64)
constexpr int P_B1   = 216;   // (8)
constexpr int P_DIST = 224;   // (64)
constexpr int P_QP   = 288;   // (64)
constexpr int P_DEP  = 352;   // (64)
constexpr int P_ARR  = 416;   // (64)
constexpr int P_MINIF= 480;   // (8)
constexpr int P_INTF = 488;   // (64)
constexpr int P_PRICE= 552;   // (64)
constexpr int P_TOTAL= 616;

constexpr int BUF = P_TOTAL;                        // shared in/out staging buffer
constexpr int BUF_FLOATS = TPB * OUTSTRIDE;         // 16896 >= 128*84=10752
constexpr int SMEM_FLOATS = BUF + BUF_FLOATS;       // 17512
constexpr int SMEM_BYTES = SMEM_FLOATS * 4;         // 70048 -> 3 blocks/SM

__device__ __forceinline__ void ld8(const float* __restrict__ s, float* r) {
    float4 a = *(const float4*)s;
    float4 b = *(const float4*)(s + 4);
    r[0] = a.x; r[1] = a.y; r[2] = a.z; r[3] = a.w;
    r[4] = b.x; r[5] = b.y; r[6] = b.z; r[7] = b.w;
}

// branch-free destination for W0 element idx (row r = idx/18, col c = idx%18)
__device__ __forceinline__ int w0_dst(int idx) {
    int r = idx / 18, c = idx % 18;
    int d;
    if (c == 0)       d = P_W0A + r;
    else if (c == 1)  d = P_W0B + r;
    else if (c < 10)  d = P_W0R + r * 8 + (c - 2);
    else              d = P_W0T + r * 8 + (c - 10);
    return d;
}

__global__ __launch_bounds__(TPB, 3)
void actnet_kernel(const float* __restrict__ x,
                   const float* __restrict__ W0, const float* __restrict__ b0,
                   const float* __restrict__ W1, const float* __restrict__ b1,
                   const float* __restrict__ distp, const float* __restrict__ qp,
                   const float* __restrict__ depf, const float* __restrict__ arrf,
                   const float* __restrict__ minif, const float* __restrict__ intf,
                   const float* __restrict__ pricef,
                   float* __restrict__ out)
{
    extern __shared__ float sm[];
    const int tid = threadIdx.x;
    const int blk = blockIdx.x;

    // ---- stage params (broadcast reads, once per block) ----
    float* Wp = sm;
    for (int idx = tid; idx < 144; idx += TPB)
        Wp[w0_dst(idx)] = W0[idx];
    for (int idx = tid; idx < 8; idx += TPB) {
        Wp[P_B0 + idx] = b0[idx];
        Wp[P_B1 + idx] = b1[idx];
        Wp[P_MINIF + idx] = minif[idx];
    }
    for (int idx = tid; idx < 64; idx += TPB) {
        Wp[P_W1 + idx] = W1[idx];
        Wp[P_DIST + idx] = distp[idx];
        Wp[P_QP + idx] = qp[idx];
        Wp[P_DEP + idx] = depf[idx];
        Wp[P_ARR + idx] = arrf[idx];
        Wp[P_INTF + idx] = intf[idx];
        Wp[P_PRICE + idx] = pricef[idx];
    }

    // ---- stage input: coalesced float4 loads -> padded smem rows ----
    const float4* x4 = (const float4*)x + (size_t)blk * (TPB * ROW / 4);
    #pragma unroll
    for (int k = 0; k < ROW / 4; k++) {            // 20 iterations
        int g = tid + k * TPB;
        float4 v = __ldg(&x4[g]);
        int row = g / 20;
        int col = (g % 20) * 4;
        *(float4*)&sm[BUF + row * INSTRIDE + col] = v;
    }
    __syncthreads();

    // ---- pull my entire row into registers (input smem dead afterwards) ----
    const float* myrow = &sm[BUF + tid * INSTRIDE];
    float veh[8], mini[8], q[64];
    ld8(&myrow[0], veh);
    ld8(&myrow[8], mini);
    #pragma unroll
    for (int r = 0; r < 8; r++) ld8(&myrow[16 + r * 8], &q[r * 8]);

    // ---- p[i] = b0 + veh*W0[:,0] + mini*W0[:,1] + q[i,:].W0R[i,:] + q[:,i].W0T[i,:] ----
    float p[8];
    {
        float b0r[8], w0a[8], w0b[8];
        ld8(&Wp[P_B0], b0r); ld8(&Wp[P_W0A], w0a); ld8(&Wp[P_W0B], w0b);
        #pragma unroll
        for (int i = 0; i < 8; i++)
            p[i] = b0r[i] + veh[i] * w0a[i] + mini[i] * w0b[i];
    }
    #pragma unroll
    for (int r = 0; r < 8; r++) {                  // direct: p[r] += q[r,:] . W0R[r,:]
        float w[8]; ld8(&Wp[P_W0R + r * 8], w);
        #pragma unroll
        for (int c = 0; c < 8; c++) p[r] += q[r * 8 + c] * w[c];
    }
    #pragma unroll
    for (int i = 0; i < 8; i++) {                  // transposed: p[i] += sum_r q[r,i]*W0T[i,r]
        float w[8]; ld8(&Wp[P_W0T + i * 8], w);
        #pragma unroll
        for (int r = 0; r < 8; r++) p[i] += q[r * 8 + i] * w[r];
    }

    // ---- potential = p @ W1^T + b1 ----
    float pot[8];
    {
        float b1r[8]; ld8(&Wp[P_B1], b1r);
        #pragma unroll
        for (int i = 0; i < 8; i++) {
            float w[8]; ld8(&Wp[P_W1 + i * 8], w);
            float a = b1r[i];
            #pragma unroll
            for (int k = 0; k < 8; k++) a += p[k] * w[k];
            pot[i] = a;
        }
    }

    // ---- remain, inv, scale (g recomputed, not stored) ----
    float remain[8], inv[8], scale[8];
    #pragma unroll
    for (int i = 0; i < 8; i++) {
        float dr[8], qpr[8];
        ld8(&Wp[P_DIST + i * 8], dr); ld8(&Wp[P_QP + i * 8], qpr);
        float rs = 0.0f;
        #pragma unroll
        for (int j = 0; j < 8; j++)
            rs += fmaxf(pot[i] - pot[j], 0.0f) * dr[j] + q[i * 8 + j] * qpr[j];
        float rem = fmaxf(veh[i] - rs, 0.0f);
        remain[i] = rem;
        float tot = fmaxf(rs + rem - 0.001f, 0.0f) + 0.001f;
        inv[i] = 1.0f / tot;
        scale[i] = veh[i] * inv[i];
    }

    // ---- departure, arrival, intentions (recompute gv) ----
    float arrival[8];
    {
        float mf[8]; ld8(&Wp[P_MINIF], mf);
        #pragma unroll
        for (int j = 0; j < 8; j++) arrival[j] = mini[j] * mf[j];
    }
    float no_remain[8];
    {
        float departure[8], intents[8];
        #pragma unroll
        for (int i = 0; i < 8; i++) {
            float dr[8], qpr[8], dep[8], arr[8], itf[8];
            ld8(&Wp[P_DIST + i * 8], dr);  ld8(&Wp[P_QP + i * 8], qpr);
            ld8(&Wp[P_DEP + i * 8], dep);  ld8(&Wp[P_ARR + i * 8], arr);
            ld8(&Wp[P_INTF + i * 8], itf);
            float sc = scale[i];
            float dsum = 0.0f, isum = 0.0f;
            #pragma unroll
            for (int j = 0; j < 8; j++) {
                float gv = fmaxf(pot[i] - pot[j], 0.0f) * dr[j] + q[i * 8 + j] * qpr[j];
                if (j == i) gv += remain[i];
                float raw = gv * sc;
                dsum += raw * dep[j];
                arrival[j] += raw * arr[j];
                isum += fmaxf(gv - raw, 0.0f) * itf[j];
            }
            departure[i] = dsum;
            intents[i] = isum;
        }
        #pragma unroll
        for (int i = 0; i < 8; i++) {
            float fv = veh[i] - departure[i] + arrival[i];
            no_remain[i] = fmaxf(fv - intents[i], 0.0f) * (1.0f / 7.0f);
        }
    }

    // ---- output: full-width staging into the (dead) input buffer ----
    __syncthreads();   // everyone done reading input smem
    {
        float* orow = &sm[BUF + tid * OUTSTRIDE];
        #pragma unroll
        for (int i = 0; i < 8; i++) {
            float dr[8], qpr[8], prf[8];
            ld8(&Wp[P_DIST + i * 8], dr); ld8(&Wp[P_QP + i * 8], qpr);
            ld8(&Wp[P_PRICE + i * 8], prf);
            float sc = scale[i], iv = inv[i], nr = no_remain[i];
            float av[8], pv[8];
            #pragma unroll
            for (int j = 0; j < 8; j++) {
                float gv = fmaxf(pot[i] - pot[j], 0.0f) * dr[j] + q[i * 8 + j] * qpr[j];
                if (j == i) gv += remain[i];
                av[j] = gv * iv;
                float raw = gv * sc;
                float fg = fmaxf(gv - raw, 0.0f);
                float fq = fmaxf(q[i * 8 + j] - raw, 0.0f);
                float it = fg + nr - fq;
                pv[j] = fmaxf(1.0f - fmaxf(it * prf[j], 0.0f) - 0.6f, 0.0f) + 0.6f;
            }
            *(float4*)&orow[i * 16 + 0]  = make_float4(av[0], av[1], av[2], av[3]);
            *(float4*)&orow[i * 16 + 4]  = make_float4(av[4], av[5], av[6], av[7]);
            *(float4*)&orow[i * 16 + 8]  = make_float4(pv[0], pv[1], pv[2], pv[3]);
            *(float4*)&orow[i * 16 + 12] = make_float4(pv[4], pv[5], pv[6], pv[7]);
        }
    }
    __syncthreads();

    // ---- flush: 128 rows * 32 float4, fully coalesced ----
    float4* out4 = (float4*)out + (size_t)blk * TPB * (OROW / 4);
    #pragma unroll
    for (int k = 0; k < 32; k++) {
        int g4 = tid + k * TPB;
        int lrow = g4 >> 5;
        int col4 = g4 & 31;
        out4[g4] = *(const float4*)&sm[BUF + lrow * OUTSTRIDE + col4 * 4];
    }
}

extern "C" void kernel_launch(void* const* d_in, const int* in_sizes, int n_in,
                              void* d_out, int out_size) {
    const float* x      = (const float*)d_in[0];
    const float* W0     = (const float*)d_in[1];
    const float* b0     = (const float*)d_in[2];
    const float* W1     = (const float*)d_in[3];
    const float* b1     = (const float*)d_in[4];
    const float* distp  = (const float*)d_in[5];
    const float* qp     = (const float*)d_in[6];
    const float* depf   = (const float*)d_in[7];
    const float* arrf   = (const float*)d_in[8];
    const float* minif  = (const float*)d_in[9];
    const float* intf   = (const float*)d_in[10];
    const float* pricef = (const float*)d_in[11];
    float* out = (float*)d_out;

    int B = in_sizes[0] / ROW;          // 262144
    int grid = B / TPB;                 // 2048

    cudaFuncSetAttribute(actnet_kernel, cudaFuncAttributeMaxDynamicSharedMemorySize, SMEM_BYTES);
    actnet_kernel<<<grid, TPB, SMEM_BYTES>>>(x, W0, b0, W1, b1, distp, qp, depf, arrf,
                                             minif, intf, pricef, out);
}

// round 6
// speedup vs baseline: 1.5174x; 1.3232x over previous
#include <cuda_runtime.h>

// ActionNetwork: B=262144 rows, N=8, M=1. 80 f32 in -> 128 f32 out per row.
// R5: 8-threads-per-row decomposition. Thread (row, i) owns row i of all 8x8
// matrices: ~55 live regs -> 4 blocks/SM (32 warps, ~48% occ). Cross-thread
// terms via shfl (p/pot gather, arrival butterfly). Lane map = i*4 + row_local
// keeps every LDS/STS pattern bank-conflict-free (INSTRIDE=88, OUTSTRIDE=132).

constexpr int TPB = 256;
constexpr int RPB = TPB / 8;     // 32 rows per block
constexpr int ROW = 80;          // floats per input row
constexpr int OROW = 128;        // floats per output row
constexpr int INSTRIDE = 88;     // input smem row stride: rows hit banks 0/24/16/8
constexpr int OUTSTRIDE = 132;   // output smem row stride: banks row*4 (+i*16) distinct

// params layout at sm[0..616), every 8-float row 16B-aligned
constexpr int P_W0A  = 0;     // W0[:,0]          (8)
constexpr int P_W0B  = 8;     // W0[:,1]          (8)
constexpr int P_W0R  = 16;    // W0[:,2:10]  8x8  (64)
constexpr int P_W0T  = 80;    // W0[:,10:18] 8x8  (64)
constexpr int P_B0   = 144;
constexpr int P_W1   = 152;
constexpr int P_B1   = 216;
constexpr int P_DIST = 224;
constexpr int P_QP   = 288;
constexpr int P_DEP  = 352;
constexpr int P_ARR  = 416;
constexpr int P_MINIF= 480;
constexpr int P_INTF = 488;
constexpr int P_PRICE= 552;
constexpr int P_TOTAL= 616;

constexpr int BUF = P_TOTAL;                       // shared in/out staging buffer
constexpr int BUF_FLOATS = RPB * OUTSTRIDE;        // 4224 >= 32*88=2816
constexpr int SMEM_FLOATS = BUF + BUF_FLOATS;      // 4840
constexpr int SMEM_BYTES = SMEM_FLOATS * 4;        // 19360 -> smem allows 10+ blocks

__device__ __forceinline__ void ld8(const float* __restrict__ s, float* r) {
    float4 a = *(const float4*)s;
    float4 b = *(const float4*)(s + 4);
    r[0] = a.x; r[1] = a.y; r[2] = a.z; r[3] = a.w;
    r[4] = b.x; r[5] = b.y; r[6] = b.z; r[7] = b.w;
}

__device__ __forceinline__ int w0_dst(int idx) {
    int r = idx / 18, c = idx % 18;
    int d;
    if (c == 0)       d = P_W0A + r;
    else if (c == 1)  d = P_W0B + r;
    else if (c < 10)  d = P_W0R + r * 8 + (c - 2);
    else              d = P_W0T + r * 8 + (c - 10);
    return d;
}

__global__ __launch_bounds__(TPB, 4)
void actnet_kernel(const float* __restrict__ x,
                   const float* __restrict__ W0, const float* __restrict__ b0,
                   const float* __restrict__ W1, const float* __restrict__ b1,
                   const float* __restrict__ distp, const float* __restrict__ qp,
                   const float* __restrict__ depf, const float* __restrict__ arrf,
                   const float* __restrict__ minif, const float* __restrict__ intf,
                   const float* __restrict__ pricef,
                   float* __restrict__ out)
{
    extern __shared__ float sm[];
    const int tid = threadIdx.x;
    const int blk = blockIdx.x;
    const int lane = tid & 31;
    const int wrp  = tid >> 5;
    const int i    = lane >> 2;        // 0..7: which matrix row this thread owns
    const int rowl = (wrp << 2) | (lane & 3);   // 0..31: data row within block

    // ---- stage params (broadcast reads, once per block) ----
    float* Wp = sm;
    for (int idx = tid; idx < 144; idx += TPB)
        Wp[w0_dst(idx)] = W0[idx];
    if (tid < 8) {
        Wp[P_B0 + tid] = b0[tid];
        Wp[P_B1 + tid] = b1[tid];
        Wp[P_MINIF + tid] = minif[tid];
    }
    if (tid >= 64 && tid < 128) {
        int idx = tid - 64;
        Wp[P_W1 + idx] = W1[idx];
        Wp[P_DIST + idx] = distp[idx];
        Wp[P_QP + idx] = qp[idx];
        Wp[P_DEP + idx] = depf[idx];
        Wp[P_ARR + idx] = arrf[idx];
        Wp[P_INTF + idx] = intf[idx];
        Wp[P_PRICE + idx] = pricef[idx];
    }

    // ---- stage input: 32 rows * 20 float4 = 640 float4, coalesced ----
    const float4* x4 = (const float4*)x + (size_t)blk * (RPB * ROW / 4);
    #pragma unroll
    for (int k = 0; k < 3; k++) {
        int g = tid + k * TPB;
        if (g < RPB * ROW / 4) {
            float4 v = __ldg(&x4[g]);
            int row = g / 20;
            int col = (g % 20) * 4;
            *(float4*)&sm[BUF + row * INSTRIDE + col] = v;
        }
    }
    __syncthreads();

    const float* myrow = &sm[BUF + rowl * INSTRIDE];

    // ---- per-thread data: veh[i], mini[i], q row i, q column i ----
    float veh_i  = myrow[i];
    float mini_i = myrow[8 + i];
    float q[8];                    // q[i][0..7]
    ld8(&myrow[16 + i * 8], q);
    float qc[8];                   // q[0..7][i]   (conflict-free scalar LDS)
    #pragma unroll
    for (int r = 0; r < 8; r++) qc[r] = myrow[16 + r * 8 + i];

    // ---- p_i = b0[i] + veh*W0A[i] + mini*W0B[i] + q[i,:].W0R[i,:] + qc.W0T[i,:] ----
    float p_i = Wp[P_B0 + i] + veh_i * Wp[P_W0A + i] + mini_i * Wp[P_W0B + i];
    {
        float w[8]; ld8(&Wp[P_W0R + i * 8], w);
        #pragma unroll
        for (int c = 0; c < 8; c++) p_i += q[c] * w[c];
    }
    {
        float w[8]; ld8(&Wp[P_W0T + i * 8], w);
        #pragma unroll
        for (int r = 0; r < 8; r++) p_i += qc[r] * w[r];
    }

    // ---- gather p, compute pot_i, gather pot ----
    const int rbase = lane & 3;    // row_local bits within lane
    float pot_i;
    {
        float pall[8];
        #pragma unroll
        for (int k = 0; k < 8; k++)
            pall[k] = __shfl_sync(0xffffffffu, p_i, (k << 2) | rbase);
        float w[8]; ld8(&Wp[P_W1 + i * 8], w);
        pot_i = Wp[P_B1 + i];
        #pragma unroll
        for (int k = 0; k < 8; k++) pot_i += pall[k] * w[k];
    }
    float pot[8];
    #pragma unroll
    for (int k = 0; k < 8; k++)
        pot[k] = __shfl_sync(0xffffffffu, pot_i, (k << 2) | rbase);

    // ---- gradient row i (stored!), remain, inv, scale ----
    float g8[8];
    float inv, scale;
    {
        float dr[8], qpr[8];
        ld8(&Wp[P_DIST + i * 8], dr); ld8(&Wp[P_QP + i * 8], qpr);
        float rs = 0.0f;
        #pragma unroll
        for (int j = 0; j < 8; j++) {
            float gv = fmaxf(pot_i - pot[j], 0.0f) * dr[j] + q[j] * qpr[j];
            g8[j] = gv;
            rs += gv;
        }
        float rem = fmaxf(veh_i - rs, 0.0f);
        #pragma unroll
        for (int j = 0; j < 8; j++) if (j == i) g8[j] += rem;
        float tot = fmaxf(rs + rem - 0.001f, 0.0f) + 0.001f;
        inv = 1.0f / tot;
        scale = veh_i * inv;
    }

    // ---- departure (local), arrival terms (butterfly), intents (local) ----
    float departure, intents;
    float acc[8];                  // arrival contributions of this thread's row
    {
        float dep[8], arr[8], itf[8];
        ld8(&Wp[P_DEP + i * 8], dep); ld8(&Wp[P_ARR + i * 8], arr);
        ld8(&Wp[P_INTF + i * 8], itf);
        float dsum = 0.0f, isum = 0.0f;
        #pragma unroll
        for (int j = 0; j < 8; j++) {
            float raw = g8[j] * scale;
            dsum += raw * dep[j];
            acc[j] = raw * arr[j];
            isum += fmaxf(g8[j] - raw, 0.0f) * itf[j];
        }
        departure = dsum;
        intents = isum;
    }
    // butterfly all-reduce over the 8 i-lanes (lane xor 4, 8, 16)
    #pragma unroll
    for (int off = 4; off <= 16; off <<= 1) {
        #pragma unroll
        for (int j = 0; j < 8; j++)
            acc[j] += __shfl_xor_sync(0xffffffffu, acc[j], off);
    }
    float arrival = mini_i * Wp[P_MINIF + i];
    #pragma unroll
    for (int j = 0; j < 8; j++) if (j == i) arrival += acc[j];

    float fv = veh_i - departure + arrival;
    float nr = fmaxf(fv - intents, 0.0f) * (1.0f / 7.0f);

    // ---- compute output row i, stage into (dead) input buffer ----
    __syncthreads();   // everyone finished reading input smem
    {
        float prf[8]; ld8(&Wp[P_PRICE + i * 8], prf);
        float av[8], pv[8];
        #pragma unroll
        for (int j = 0; j < 8; j++) {
            float gv = g8[j];
            av[j] = gv * inv;
            float raw = gv * scale;
            float fg = fmaxf(gv - raw, 0.0f);
            float fq = fmaxf(q[j] - raw, 0.0f);
            float it = fg + nr - fq;
            pv[j] = fmaxf(1.0f - fmaxf(it * prf[j], 0.0f) - 0.6f, 0.0f) + 0.6f;
        }
        float* orow = &sm[BUF + rowl * OUTSTRIDE + i * 16];
        *(float4*)&orow[0]  = make_float4(av[0], av[1], av[2], av[3]);
        *(float4*)&orow[4]  = make_float4(av[4], av[5], av[6], av[7]);
        *(float4*)&orow[8]  = make_float4(pv[0], pv[1], pv[2], pv[3]);
        *(float4*)&orow[12] = make_float4(pv[4], pv[5], pv[6], pv[7]);
    }
    __syncthreads();

    // ---- flush: 32 rows * 32 float4 = 1024 float4, fully coalesced ----
    float4* out4 = (float4*)out + (size_t)blk * RPB * (OROW / 4);
    #pragma unroll
    for (int k = 0; k < 4; k++) {
        int g4 = tid + k * TPB;
        int lrow = g4 >> 5;
        int col4 = g4 & 31;
        out4[g4] = *(const float4*)&sm[BUF + lrow * OUTSTRIDE + col4 * 4];
    }
}

extern "C" void kernel_launch(void* const* d_in, const int* in_sizes, int n_in,
                              void* d_out, int out_size) {
    const float* x      = (const float*)d_in[0];
    const float* W0     = (const float*)d_in[1];
    const float* b0     = (const float*)d_in[2];
    const float* W1     = (const float*)d_in[3];
    const float* b1     = (const float*)d_in[4];
    const float* distp  = (const float*)d_in[5];
    const float* qp     = (const float*)d_in[6];
    const float* depf   = (const float*)d_in[7];
    const float* arrf   = (const float*)d_in[8];
    const float* minif  = (const float*)d_in[9];
    const float* intf   = (const float*)d_in[10];
    const float* pricef = (const float*)d_in[11];
    float* out = (float*)d_out;

    int B = in_sizes[0] / ROW;          // 262144
    int grid = B / RPB;                 // 8192

    cudaFuncSetAttribute(actnet_kernel, cudaFuncAttributeMaxDynamicSharedMemorySize, SMEM_BYTES);
    actnet_kernel<<<grid, TPB, SMEM_BYTES>>>(x, W0, b0, W1, b1, distp, qp, depf, arrf,
                                             minif, intf, pricef, out);
}

// round 8
// speedup vs baseline: 1.5182x; 1.0005x over previous
#include <cuda_runtime.h>

// ActionNetwork: B=262144 rows, N=8, M=1. 80 f32 in -> 128 f32 out per row.
// R5: 8-threads-per-row decomposition. Thread (row, i) owns row i of all 8x8
// matrices: ~55 live regs -> 4 blocks/SM (32 warps, ~48% occ). Cross-thread
// terms via shfl (p/pot gather, arrival butterfly). Lane map = i*4 + row_local
// keeps every LDS/STS pattern bank-conflict-free (INSTRIDE=88, OUTSTRIDE=132).

constexpr int TPB = 256;
constexpr int RPB = TPB / 8;     // 32 rows per block
constexpr int ROW = 80;          // floats per input row
constexpr int OROW = 128;        // floats per output row
constexpr int INSTRIDE = 88;     // input smem row stride: rows hit banks 0/24/16/8
constexpr int OUTSTRIDE = 132;   // output smem row stride: banks row*4 (+i*16) distinct

// params layout at sm[0..616), every 8-float row 16B-aligned
constexpr int P_W0A  = 0;     // W0[:,0]          (8)
constexpr int P_W0B  = 8;     // W0[:,1]          (8)
constexpr int P_W0R  = 16;    // W0[:,2:10]  8x8  (64)
constexpr int P_W0T  = 80;    // W0[:,10:18] 8x8  (64)
constexpr int P_B0   = 144;
constexpr int P_W1   = 152;
constexpr int P_B1   = 216;
constexpr int P_DIST = 224;
constexpr int P_QP   = 288;
constexpr int P_DEP  = 352;
constexpr int P_ARR  = 416;
constexpr int P_MINIF= 480;
constexpr int P_INTF = 488;
constexpr int P_PRICE= 552;
constexpr int P_TOTAL= 616;

constexpr int BUF = P_TOTAL;                       // shared in/out staging buffer
constexpr int BUF_FLOATS = RPB * OUTSTRIDE;        // 4224 >= 32*88=2816
constexpr int SMEM_FLOATS = BUF + BUF_FLOATS;      // 4840
constexpr int SMEM_BYTES = SMEM_FLOATS * 4;        // 19360 -> smem allows 10+ blocks

__device__ __forceinline__ void ld8(const float* __restrict__ s, float* r) {
    float4 a = *(const float4*)s;
    float4 b = *(const float4*)(s + 4);
    r[0] = a.x; r[1] = a.y; r[2] = a.z; r[3] = a.w;
    r[4] = b.x; r[5] = b.y; r[6] = b.z; r[7] = b.w;
}

__device__ __forceinline__ int w0_dst(int idx) {
    int r = idx / 18, c = idx % 18;
    int d;
    if (c == 0)       d = P_W0A + r;
    else if (c == 1)  d = P_W0B + r;
    else if (c < 10)  d = P_W0R + r * 8 + (c - 2);
    else              d = P_W0T + r * 8 + (c - 10);
    return d;
}

__global__ __launch_bounds__(TPB, 4)
void actnet_kernel(const float* __restrict__ x,
                   const float* __restrict__ W0, const float* __restrict__ b0,
                   const float* __restrict__ W1, const float* __restrict__ b1,
                   const float* __restrict__ distp, const float* __restrict__ qp,
                   const float* __restrict__ depf, const float* __restrict__ arrf,
                   const float* __restrict__ minif, const float* __restrict__ intf,
                   const float* __restrict__ pricef,
                   float* __restrict__ out)
{
    extern __shared__ float sm[];
    const int tid = threadIdx.x;
    const int blk = blockIdx.x;
    const int lane = tid & 31;
    const int wrp  = tid >> 5;
    const int i    = lane >> 2;        // 0..7: which matrix row this thread owns
    const int rowl = (wrp << 2) | (lane & 3);   // 0..31: data row within block

    // ---- stage params (broadcast reads, once per block) ----
    float* Wp = sm;
    for (int idx = tid; idx < 144; idx += TPB)
        Wp[w0_dst(idx)] = W0[idx];
    if (tid < 8) {
        Wp[P_B0 + tid] = b0[tid];
        Wp[P_B1 + tid] = b1[tid];
        Wp[P_MINIF + tid] = minif[tid];
    }
    if (tid >= 64 && tid < 128) {
        int idx = tid - 64;
        Wp[P_W1 + idx] = W1[idx];
        Wp[P_DIST + idx] = distp[idx];
        Wp[P_QP + idx] = qp[idx];
        Wp[P_DEP + idx] = depf[idx];
        Wp[P_ARR + idx] = arrf[idx];
        Wp[P_INTF + idx] = intf[idx];
        Wp[P_PRICE + idx] = pricef[idx];
    }

    // ---- stage input: 32 rows * 20 float4 = 640 float4, coalesced ----
    const float4* x4 = (const float4*)x + (size_t)blk * (RPB * ROW / 4);
    #pragma unroll
    for (int k = 0; k < 3; k++) {
        int g = tid + k * TPB;
        if (g < RPB * ROW / 4) {
            float4 v = __ldg(&x4[g]);
            int row = g / 20;
            int col = (g % 20) * 4;
            *(float4*)&sm[BUF + row * INSTRIDE + col] = v;
        }
    }
    __syncthreads();

    const float* myrow = &sm[BUF + rowl * INSTRIDE];

    // ---- per-thread data: veh[i], mini[i], q row i, q column i ----
    float veh_i  = myrow[i];
    float mini_i = myrow[8 + i];
    float q[8];                    // q[i][0..7]
    ld8(&myrow[16 + i * 8], q);
    float qc[8];                   // q[0..7][i]   (conflict-free scalar LDS)
    #pragma unroll
    for (int r = 0; r < 8; r++) qc[r] = myrow[16 + r * 8 + i];

    // ---- p_i = b0[i] + veh*W0A[i] + mini*W0B[i] + q[i,:].W0R[i,:] + qc.W0T[i,:] ----
    float p_i = Wp[P_B0 + i] + veh_i * Wp[P_W0A + i] + mini_i * Wp[P_W0B + i];
    {
        float w[8]; ld8(&Wp[P_W0R + i * 8], w);
        #pragma unroll
        for (int c = 0; c < 8; c++) p_i += q[c] * w[c];
    }
    {
        float w[8]; ld8(&Wp[P_W0T + i * 8], w);
        #pragma unroll
        for (int r = 0; r < 8; r++) p_i += qc[r] * w[r];
    }

    // ---- gather p, compute pot_i, gather pot ----
    const int rbase = lane & 3;    // row_local bits within lane
    float pot_i;
    {
        float pall[8];
        #pragma unroll
        for (int k = 0; k < 8; k++)
            pall[k] = __shfl_sync(0xffffffffu, p_i, (k << 2) | rbase);
        float w[8]; ld8(&Wp[P_W1 + i * 8], w);
        pot_i = Wp[P_B1 + i];
        #pragma unroll
        for (int k = 0; k < 8; k++) pot_i += pall[k] * w[k];
    }
    float pot[8];
    #pragma unroll
    for (int k = 0; k < 8; k++)
        pot[k] = __shfl_sync(0xffffffffu, pot_i, (k << 2) | rbase);

    // ---- gradient row i (stored!), remain, inv, scale ----
    float g8[8];
    float inv, scale;
    {
        float dr[8], qpr[8];
        ld8(&Wp[P_DIST + i * 8], dr); ld8(&Wp[P_QP + i * 8], qpr);
        float rs = 0.0f;
        #pragma unroll
        for (int j = 0; j < 8; j++) {
            float gv = fmaxf(pot_i - pot[j], 0.0f) * dr[j] + q[j] * qpr[j];
            g8[j] = gv;
            rs += gv;
        }
        float rem = fmaxf(veh_i - rs, 0.0f);
        #pragma unroll
        for (int j = 0; j < 8; j++) if (j == i) g8[j] += rem;
        float tot = fmaxf(rs + rem - 0.001f, 0.0f) + 0.001f;
        inv = 1.0f / tot;
        scale = veh_i * inv;
    }

    // ---- departure (local), arrival terms (butterfly), intents (local) ----
    float departure, intents;
    float acc[8];                  // arrival contributions of this thread's row
    {
        float dep[8], arr[8], itf[8];
        ld8(&Wp[P_DEP + i * 8], dep); ld8(&Wp[P_ARR + i * 8], arr);
        ld8(&Wp[P_INTF + i * 8], itf);
        float dsum = 0.0f, isum = 0.0f;
        #pragma unroll
        for (int j = 0; j < 8; j++) {
            float raw = g8[j] * scale;
            dsum += raw * dep[j];
            acc[j] = raw * arr[j];
            isum += fmaxf(g8[j] - raw, 0.0f) * itf[j];
        }
        departure = dsum;
        intents = isum;
    }
    // butterfly all-reduce over the 8 i-lanes (lane xor 4, 8, 16)
    #pragma unroll
    for (int off = 4; off <= 16; off <<= 1) {
        #pragma unroll
        for (int j = 0; j < 8; j++)
            acc[j] += __shfl_xor_sync(0xffffffffu, acc[j], off);
    }
    float arrival = mini_i * Wp[P_MINIF + i];
    #pragma unroll
    for (int j = 0; j < 8; j++) if (j == i) arrival += acc[j];

    float fv = veh_i - departure + arrival;
    float nr = fmaxf(fv - intents, 0.0f) * (1.0f / 7.0f);

    // ---- compute output row i, stage into (dead) input buffer ----
    __syncthreads();   // everyone finished reading input smem
    {
        float prf[8]; ld8(&Wp[P_PRICE + i * 8], prf);
        float av[8], pv[8];
        #pragma unroll
        for (int j = 0; j < 8; j++) {
            float gv = g8[j];
            av[j] = gv * inv;
            float raw = gv * scale;
            float fg = fmaxf(gv - raw, 0.0f);
            float fq = fmaxf(q[j] - raw, 0.0f);
            float it = fg + nr - fq;
            pv[j] = fmaxf(1.0f - fmaxf(it * prf[j], 0.0f) - 0.6f, 0.0f) + 0.6f;
        }
        float* orow = &sm[BUF + rowl * OUTSTRIDE + i * 16];
        *(float4*)&orow[0]  = make_float4(av[0], av[1], av[2], av[3]);
        *(float4*)&orow[4]  = make_float4(av[4], av[5], av[6], av[7]);
        *(float4*)&orow[8]  = make_float4(pv[0], pv[1], pv[2], pv[3]);
        *(float4*)&orow[12] = make_float4(pv[4], pv[5], pv[6], pv[7]);
    }
    __syncthreads();

    // ---- flush: 32 rows * 32 float4 = 1024 float4, fully coalesced ----
    float4* out4 = (float4*)out + (size_t)blk * RPB * (OROW / 4);
    #pragma unroll
    for (int k = 0; k < 4; k++) {
        int g4 = tid + k * TPB;
        int lrow = g4 >> 5;
        int col4 = g4 & 31;
        out4[g4] = *(const float4*)&sm[BUF + lrow * OUTSTRIDE + col4 * 4];
    }
}

extern "C" void kernel_launch(void* const* d_in, const int* in_sizes, int n_in,
                              void* d_out, int out_size) {
    const float* x      = (const float*)d_in[0];
    const float* W0     = (const float*)d_in[1];
    const float* b0     = (const float*)d_in[2];
    const float* W1     = (const float*)d_in[3];
    const float* b1     = (const float*)d_in[4];
    const float* distp  = (const float*)d_in[5];
    const float* qp     = (const float*)d_in[6];
    const float* depf   = (const float*)d_in[7];
    const float* arrf   = (const float*)d_in[8];
    const float* minif  = (const float*)d_in[9];
    const float* intf   = (const float*)d_in[10];
    const float* pricef = (const float*)d_in[11];
    float* out = (float*)d_out;

    int B = in_sizes[0] / ROW;          // 262144
    int grid = B / RPB;                 // 8192

    cudaFuncSetAttribute(actnet_kernel, cudaFuncAttributeMaxDynamicSharedMemorySize, SMEM_BYTES);
    actnet_kernel<<<grid, TPB, SMEM_BYTES>>>(x, W0, b0, W1, b1, distp, qp, depf, arrf,
                                             minif, intf, pricef, out);
}